// round 3
// baseline (speedup 1.0000x reference)
#include <cuda_runtime.h>

#define NNODES 65536
#define NC 256

// Persistent scratch (no allocations allowed)
__device__ float g_bufA[NNODES * NC];   // xt (NHWC nodes) -> later agg
__device__ float g_bufB[NNODES * NC];   // conv_out -> later g
__device__ float g_nodes[NNODES * NC];  // bn2d+relu node features
__device__ float g_wt[9 * NC * NC];     // conv weights [tap][ci][co]
__device__ float g_wcat[512 * NC];      // [k][co]: k<256 -> w_rel^T, k>=256 -> w_root^T
__device__ float g_stats[1024];         // sum2d, sumsq2d, sum1d, sumsq1d
__device__ float g_coef[1024];          // sc2d, sh2d, sc1d, sh1d
__device__ int   g_is32;                // edge_index dtype flag

// ---------------- transpose x: NCHW -> node-major [node][c] ----------------
__global__ void k_transpose_x(const float* __restrict__ x) {
    __shared__ float tile[256 * 33];
    int bh = blockIdx.x;            // b*32 + h
    int b = bh >> 5, h = bh & 31;
    for (int i = threadIdx.x; i < 8192; i += 256) {
        int c = i >> 5, w = i & 31;
        tile[c * 33 + w] = x[((b * NC + c) * 32 + h) * 32 + w];
    }
    __syncthreads();
    int nb = bh * 32;
    for (int i = threadIdx.x; i < 8192; i += 256) {
        int w = i >> 8, c = i & 255;
        g_bufA[(nb + w) * NC + c] = tile[c * 33 + w];
    }
}

// ---------------- weight prep + stats zero ----------------
__global__ void k_prep(const float* __restrict__ cw,
                       const float* __restrict__ wrel,
                       const float* __restrict__ wroot) {
    int i = blockIdx.x * 256 + threadIdx.x;
    if (i < 9 * NC * NC) {
        int tap = i % 9;
        int t = i / 9;
        int ci = t % NC, co = t / NC;
        g_wt[(tap * NC + ci) * NC + co] = cw[i];
    }
    if (i < 512 * NC) {
        int k = i >> 8, co = i & 255;
        g_wcat[i] = (k < NC) ? wrel[co * NC + k] : wroot[co * NC + (k - NC)];
    }
    if (blockIdx.x == 0) {
        for (int j = threadIdx.x; j < 1024; j += 256) g_stats[j] = 0.f;
    }
}

// ---------------- edge dtype detection (single block -> no race) ----------------
__global__ void k_detect(const int* __restrict__ ei32) {
    __shared__ int any;
    if (threadIdx.x == 0) any = 0;
    __syncthreads();
    int a = 0;
    for (int j = threadIdx.x; j < 8192; j += 256) a |= ei32[2 * j + 1];
    if (a) atomicOr(&any, 1);
    __syncthreads();
    if (threadIdx.x == 0) g_is32 = (any != 0) ? 1 : 0;
}

// ---------------- conv 3x3 as implicit GEMM ----------------
// out[node][co] = sum_{tap,c} xt[nbr(node,tap)][c] * wt[tap][c][co] + bias[co]
__global__ __launch_bounds__(256) void k_conv(const float* __restrict__ bias) {
    __shared__ float As[128 * 36];   // [m][k] padded
    __shared__ float Bs[32 * 128];   // [k][n]
    int mbase = blockIdx.x * 128;
    int nbase = blockIdx.y * 128;
    int tid = threadIdx.x;
    int tx = tid & 15, ty = tid >> 4;
    int m0 = ty * 8, n0 = tx * 8;
    float acc[8][8] = {};

    for (int tap = 0; tap < 9; tap++) {
        int dy = tap / 3 - 1, dx = tap % 3 - 1;
        int nofs = dy * 32 + dx;
        for (int kc = 0; kc < 8; kc++) {
            #pragma unroll
            for (int i = 0; i < 4; i++) {
                int s = tid + i * 256;
                int m = s >> 3, cq = s & 7;
                int node = mbase + m;
                int hh = ((node >> 5) & 31) + dy;
                int ww = (node & 31) + dx;
                float4 v = make_float4(0.f, 0.f, 0.f, 0.f);
                if ((unsigned)hh < 32u && (unsigned)ww < 32u)
                    v = *(const float4*)&g_bufA[(node + nofs) * NC + kc * 32 + cq * 4];
                *(float4*)&As[m * 36 + cq * 4] = v;
            }
            #pragma unroll
            for (int i = 0; i < 4; i++) {
                int s = tid + i * 256;
                int k = s >> 5, n4 = s & 31;
                *(float4*)&Bs[k * 128 + n4 * 4] =
                    *(const float4*)&g_wt[(tap * NC + kc * 32 + k) * NC + nbase + n4 * 4];
            }
            __syncthreads();
            #pragma unroll 8
            for (int kk = 0; kk < 32; kk++) {
                float a[8];
                #pragma unroll
                for (int i = 0; i < 8; i++) a[i] = As[(m0 + i) * 36 + kk];
                float4 b0 = *(float4*)&Bs[kk * 128 + n0];
                float4 b1 = *(float4*)&Bs[kk * 128 + n0 + 4];
                float bb[8] = {b0.x, b0.y, b0.z, b0.w, b1.x, b1.y, b1.z, b1.w};
                #pragma unroll
                for (int i = 0; i < 8; i++)
                    #pragma unroll
                    for (int j = 0; j < 8; j++) acc[i][j] = fmaf(a[i], bb[j], acc[i][j]);
            }
            __syncthreads();
        }
    }
    float bb[8];
    #pragma unroll
    for (int j = 0; j < 8; j++) bb[j] = bias[nbase + n0 + j];
    #pragma unroll
    for (int i = 0; i < 8; i++) {
        int row = mbase + m0 + i;
        float4 v0 = make_float4(acc[i][0] + bb[0], acc[i][1] + bb[1],
                                acc[i][2] + bb[2], acc[i][3] + bb[3]);
        float4 v1 = make_float4(acc[i][4] + bb[4], acc[i][5] + bb[5],
                                acc[i][6] + bb[6], acc[i][7] + bb[7]);
        *(float4*)&g_bufB[row * NC + nbase + n0] = v0;
        *(float4*)&g_bufB[row * NC + nbase + n0 + 4] = v1;
    }
}

// ---------------- per-channel sum/sumsq over g_bufB ----------------
__global__ void k_stats(int so) {
    int c = threadIdx.x;
    int r0 = blockIdx.x * 64;
    float s = 0.f, ss = 0.f;
    #pragma unroll 4
    for (int r = 0; r < 64; r++) {
        float v = g_bufB[(r0 + r) * NC + c];
        s += v;
        ss += v * v;
    }
    atomicAdd(&g_stats[so + c], s);
    atomicAdd(&g_stats[so + 256 + c], ss);
}

__global__ void k_coef(int so, const float* __restrict__ gamma,
                       const float* __restrict__ beta, int co) {
    int c = threadIdx.x;
    float mean = g_stats[so + c] * (1.f / NNODES);
    float var  = g_stats[so + 256 + c] * (1.f / NNODES) - mean * mean;
    float sc = gamma[c] * rsqrtf(var + 1e-5f);
    g_coef[co + c] = sc;
    g_coef[co + 256 + c] = beta[c] - mean * sc;
}

// ---------------- bn2d+relu -> nodes ; zero agg ----------------
__global__ void k_bnrelu_zero() {
    int idx = blockIdx.x * 256 + threadIdx.x;  // float4 index, 4194304 total
    int c4 = idx & 63;
    float4 v  = ((const float4*)g_bufB)[idx];
    float4 sc = ((const float4*)g_coef)[c4];
    float4 sh = ((const float4*)(g_coef + 256))[c4];
    v.x = fmaxf(fmaf(v.x, sc.x, sh.x), 0.f);
    v.y = fmaxf(fmaf(v.y, sc.y, sh.y), 0.f);
    v.z = fmaxf(fmaf(v.z, sc.z, sh.z), 0.f);
    v.w = fmaxf(fmaf(v.w, sc.w, sh.w), 0.f);
    ((float4*)g_nodes)[idx] = v;
    ((float4*)g_bufA)[idx] = make_float4(0.f, 0.f, 0.f, 0.f);
}

// ---------------- edge scatter-add: agg[dst] += nodes[src] ----------------
__global__ void k_scatter(const void* __restrict__ ei, int E) {
    int e = blockIdx.x * 8 + (threadIdx.x >> 5);
    if (e >= E) return;
    int lane = threadIdx.x & 31;
    int src, dst;
    if (g_is32) {
        const int* p = (const int*)ei;
        src = p[e]; dst = p[E + e];
    } else {
        const long long* p = (const long long*)ei;
        src = (int)p[e]; dst = (int)p[E + e];
    }
    const float4* sp = (const float4*)&g_nodes[src * NC];
    float4* dp = (float4*)&g_bufA[dst * NC];
    #pragma unroll
    for (int i = 0; i < 2; i++) {
        float4 v = sp[lane + i * 32];
        float4* p4 = dp + lane + i * 32;
        asm volatile("red.global.add.v4.f32 [%0], {%1,%2,%3,%4};"
                     :: "l"(p4), "f"(v.x), "f"(v.y), "f"(v.z), "f"(v.w)
                     : "memory");
    }
}

// ---------------- graph GEMM: g = [agg|nodes] @ wcat + b_rel ----------------
__global__ __launch_bounds__(256) void k_gemm(const float* __restrict__ brel) {
    __shared__ float As[128 * 36];
    __shared__ float Bs[32 * 128];
    int mbase = blockIdx.x * 128;
    int nbase = blockIdx.y * 128;
    int tid = threadIdx.x;
    int tx = tid & 15, ty = tid >> 4;
    int m0 = ty * 8, n0 = tx * 8;
    float acc[8][8] = {};

    for (int kc = 0; kc < 16; kc++) {
        const float* src = (kc < 8) ? g_bufA : g_nodes;
        int coff = (kc & 7) * 32;
        #pragma unroll
        for (int i = 0; i < 4; i++) {
            int s = tid + i * 256;
            int m = s >> 3, cq = s & 7;
            *(float4*)&As[m * 36 + cq * 4] =
                *(const float4*)&src[(mbase + m) * NC + coff + cq * 4];
        }
        #pragma unroll
        for (int i = 0; i < 4; i++) {
            int s = tid + i * 256;
            int k = s >> 5, n4 = s & 31;
            *(float4*)&Bs[k * 128 + n4 * 4] =
                *(const float4*)&g_wcat[(kc * 32 + k) * NC + nbase + n4 * 4];
        }
        __syncthreads();
        #pragma unroll 8
        for (int kk = 0; kk < 32; kk++) {
            float a[8];
            #pragma unroll
            for (int i = 0; i < 8; i++) a[i] = As[(m0 + i) * 36 + kk];
            float4 b0 = *(float4*)&Bs[kk * 128 + n0];
            float4 b1 = *(float4*)&Bs[kk * 128 + n0 + 4];
            float bb[8] = {b0.x, b0.y, b0.z, b0.w, b1.x, b1.y, b1.z, b1.w};
            #pragma unroll
            for (int i = 0; i < 8; i++)
                #pragma unroll
                for (int j = 0; j < 8; j++) acc[i][j] = fmaf(a[i], bb[j], acc[i][j]);
        }
        __syncthreads();
    }
    float bb[8];
    #pragma unroll
    for (int j = 0; j < 8; j++) bb[j] = brel[nbase + n0 + j];
    #pragma unroll
    for (int i = 0; i < 8; i++) {
        int row = mbase + m0 + i;
        float4 v0 = make_float4(acc[i][0] + bb[0], acc[i][1] + bb[1],
                                acc[i][2] + bb[2], acc[i][3] + bb[3]);
        float4 v1 = make_float4(acc[i][4] + bb[4], acc[i][5] + bb[5],
                                acc[i][6] + bb[6], acc[i][7] + bb[7]);
        *(float4*)&g_bufB[row * NC + nbase + n0] = v0;
        *(float4*)&g_bufB[row * NC + nbase + n0 + 4] = v1;
    }
}

// ---------------- bn1d+relu, transpose back to NCHW, residual ----------------
__global__ void k_final(const float* __restrict__ x, float* __restrict__ out) {
    __shared__ float tile[32 * 257];
    int bh = blockIdx.x;
    int b = bh >> 5, h = bh & 31;
    int nb = bh * 32;
    for (int i = threadIdx.x; i < 8192; i += 256) {
        int w = i >> 8, c = i & 255;
        tile[w * 257 + c] = g_bufB[(nb + w) * NC + c];
    }
    __syncthreads();
    for (int i = threadIdx.x; i < 8192; i += 256) {
        int c = i >> 5, w = i & 31;
        float v = fmaf(tile[w * 257 + c], g_coef[512 + c], g_coef[768 + c]);
        v = fmaxf(v, 0.f);
        int o = ((b * NC + c) * 32 + h) * 32 + w;
        out[o] = v + x[o];
    }
}

extern "C" void kernel_launch(void* const* d_in, const int* in_sizes, int n_in,
                              void* d_out, int out_size) {
    const float* x      = (const float*)d_in[0];
    const void*  ei     = d_in[1];
    const float* conv_w = (const float*)d_in[2];
    const float* conv_b = (const float*)d_in[3];
    const float* bn2d_g = (const float*)d_in[4];
    const float* bn2d_b = (const float*)d_in[5];
    const float* w_rel  = (const float*)d_in[6];
    const float* b_rel  = (const float*)d_in[7];
    const float* w_root = (const float*)d_in[8];
    const float* bn1d_g = (const float*)d_in[9];
    const float* bn1d_b = (const float*)d_in[10];
    float* out = (float*)d_out;
    int E = in_sizes[1] / 2;

    k_transpose_x<<<2048, 256>>>(x);
    k_prep<<<2304, 256>>>(conv_w, w_rel, w_root);
    k_detect<<<1, 256>>>((const int*)ei);
    k_conv<<<dim3(512, 2), 256>>>(conv_b);
    k_stats<<<1024, 256>>>(0);
    k_coef<<<1, 256>>>(0, bn2d_g, bn2d_b, 0);
    k_bnrelu_zero<<<16384, 256>>>();
    k_scatter<<<(E + 7) / 8, 256>>>(ei, E);
    k_gemm<<<dim3(512, 2), 256>>>(b_rel);
    k_stats<<<1024, 256>>>(512);
    k_coef<<<1, 256>>>(512, bn1d_g, bn1d_b, 512);
    k_final<<<2048, 256>>>(x, out);
}

// round 5
// speedup vs baseline: 1.5958x; 1.5958x over previous
#include <cuda_runtime.h>

#define NNODES 65536
#define NC 256

typedef unsigned long long u64;

// Persistent scratch (no allocations allowed)
__device__ float g_bufA[NNODES * NC];   // xt (NHWC nodes) -> later agg
__device__ float g_bufB[NNODES * NC];   // conv_out -> later g
__device__ float g_nodes[NNODES * NC];  // bn2d+relu node features
__device__ float g_wt[9 * NC * NC];     // conv weights [tap][ci][co]
__device__ float g_wcat[512 * NC];      // [k][co]: k<256 -> w_rel^T, k>=256 -> w_root^T
__device__ float g_stats[1024];         // sum2d, sumsq2d, sum1d, sumsq1d
__device__ float g_coef[1024];          // sc2d, sh2d, sc1d, sh1d
__device__ int   g_is32;                // edge_index dtype flag

// packed f32x2 helpers
__device__ __forceinline__ u64 pack_dup(float a) {
    u64 r;
    asm("mov.b64 %0, {%1, %1};" : "=l"(r) : "f"(a));
    return r;
}
__device__ __forceinline__ void fma2(u64& d, u64 a, u64 b) {
    asm("fma.rn.f32x2 %0, %1, %2, %0;" : "+l"(d) : "l"(a), "l"(b));
}
__device__ __forceinline__ void unpack2(u64 v, float& lo, float& hi) {
    asm("mov.b64 {%0, %1}, %2;" : "=f"(lo), "=f"(hi) : "l"(v));
}

// ---------------- transpose x: NCHW -> node-major [node][c] ----------------
__global__ void k_transpose_x(const float* __restrict__ x) {
    __shared__ float tile[256 * 33];
    int bh = blockIdx.x;            // b*32 + h
    int b = bh >> 5, h = bh & 31;
    for (int i = threadIdx.x; i < 8192; i += 256) {
        int c = i >> 5, w = i & 31;
        tile[c * 33 + w] = x[((b * NC + c) * 32 + h) * 32 + w];
    }
    __syncthreads();
    int nb = bh * 32;
    for (int i = threadIdx.x; i < 8192; i += 256) {
        int w = i >> 8, c = i & 255;
        g_bufA[(nb + w) * NC + c] = tile[c * 33 + w];
    }
}

// ---------------- weight prep + stats zero ----------------
__global__ void k_prep(const float* __restrict__ cw,
                       const float* __restrict__ wrel,
                       const float* __restrict__ wroot) {
    int i = blockIdx.x * 256 + threadIdx.x;
    if (i < 9 * NC * NC) {
        int tap = i % 9;
        int t = i / 9;
        int ci = t % NC, co = t / NC;
        g_wt[(tap * NC + ci) * NC + co] = cw[i];
    }
    if (i < 512 * NC) {
        int k = i >> 8, co = i & 255;
        g_wcat[i] = (k < NC) ? wrel[co * NC + k] : wroot[co * NC + (k - NC)];
    }
    if (blockIdx.x == 0) {
        for (int j = threadIdx.x; j < 1024; j += 256) g_stats[j] = 0.f;
    }
}

// ---------------- edge dtype detection (single block -> no race) ----------------
__global__ void k_detect(const int* __restrict__ ei32) {
    __shared__ int any;
    if (threadIdx.x == 0) any = 0;
    __syncthreads();
    int a = 0;
    for (int j = threadIdx.x; j < 8192; j += 256) a |= ei32[2 * j + 1];
    if (a) atomicOr(&any, 1);
    __syncthreads();
    if (threadIdx.x == 0) g_is32 = (any != 0) ? 1 : 0;
}

// ---------------- conv 3x3 as implicit GEMM (packed f32x2 math) ----------------
__global__ __launch_bounds__(256) void k_conv(const float* __restrict__ bias) {
    __shared__ float As[128 * 36];   // [m][k] padded
    __shared__ float Bs[32 * 128];   // [k][n]
    int mbase = blockIdx.x * 128;
    int nbase = blockIdx.y * 128;
    int tid = threadIdx.x;
    int tx = tid & 15, ty = tid >> 4;
    int m0 = ty * 8, n0 = tx * 8;
    u64 acc[8][4] = {};              // [m][n-pair]

    for (int tap = 0; tap < 9; tap++) {
        int dy = tap / 3 - 1, dx = tap % 3 - 1;
        int nofs = dy * 32 + dx;
        for (int kc = 0; kc < 8; kc++) {
            #pragma unroll
            for (int i = 0; i < 4; i++) {
                int s = tid + i * 256;
                int m = s >> 3, cq = s & 7;
                int node = mbase + m;
                int hh = ((node >> 5) & 31) + dy;
                int ww = (node & 31) + dx;
                float4 v = make_float4(0.f, 0.f, 0.f, 0.f);
                if ((unsigned)hh < 32u && (unsigned)ww < 32u)
                    v = *(const float4*)&g_bufA[(node + nofs) * NC + kc * 32 + cq * 4];
                *(float4*)&As[m * 36 + cq * 4] = v;
            }
            #pragma unroll
            for (int i = 0; i < 4; i++) {
                int s = tid + i * 256;
                int k = s >> 5, n4 = s & 31;
                *(float4*)&Bs[k * 128 + n4 * 4] =
                    *(const float4*)&g_wt[(tap * NC + kc * 32 + k) * NC + nbase + n4 * 4];
            }
            __syncthreads();
            #pragma unroll 8
            for (int kk = 0; kk < 32; kk++) {
                u64 aa[8];
                #pragma unroll
                for (int i = 0; i < 8; i++) aa[i] = pack_dup(As[(m0 + i) * 36 + kk]);
                const u64* bp = (const u64*)&Bs[kk * 128 + n0];
                u64 b0 = bp[0], b1 = bp[1], b2 = bp[2], b3 = bp[3];
                #pragma unroll
                for (int i = 0; i < 8; i++) {
                    fma2(acc[i][0], aa[i], b0);
                    fma2(acc[i][1], aa[i], b1);
                    fma2(acc[i][2], aa[i], b2);
                    fma2(acc[i][3], aa[i], b3);
                }
            }
            __syncthreads();
        }
    }
    float bb[8];
    #pragma unroll
    for (int j = 0; j < 8; j++) bb[j] = bias[nbase + n0 + j];
    #pragma unroll
    for (int i = 0; i < 8; i++) {
        int row = mbase + m0 + i;
        float r[8];
        #pragma unroll
        for (int j = 0; j < 4; j++) unpack2(acc[i][j], r[2 * j], r[2 * j + 1]);
        float4 v0 = make_float4(r[0] + bb[0], r[1] + bb[1], r[2] + bb[2], r[3] + bb[3]);
        float4 v1 = make_float4(r[4] + bb[4], r[5] + bb[5], r[6] + bb[6], r[7] + bb[7]);
        *(float4*)&g_bufB[row * NC + nbase + n0] = v0;
        *(float4*)&g_bufB[row * NC + nbase + n0 + 4] = v1;
    }
}

// ---------------- per-channel sum/sumsq over g_bufB ----------------
__global__ void k_stats(int so) {
    int c = threadIdx.x;
    int r0 = blockIdx.x * 64;
    float s = 0.f, ss = 0.f;
    #pragma unroll 4
    for (int r = 0; r < 64; r++) {
        float v = g_bufB[(r0 + r) * NC + c];
        s += v;
        ss += v * v;
    }
    atomicAdd(&g_stats[so + c], s);
    atomicAdd(&g_stats[so + 256 + c], ss);
}

__global__ void k_coef(int so, const float* __restrict__ gamma,
                       const float* __restrict__ beta, int co) {
    int c = threadIdx.x;
    float mean = g_stats[so + c] * (1.f / NNODES);
    float var  = g_stats[so + 256 + c] * (1.f / NNODES) - mean * mean;
    float sc = gamma[c] * rsqrtf(var + 1e-5f);
    g_coef[co + c] = sc;
    g_coef[co + 256 + c] = beta[c] - mean * sc;
}

// ---------------- bn2d+relu -> nodes ; zero agg ----------------
__global__ void k_bnrelu_zero() {
    int idx = blockIdx.x * 256 + threadIdx.x;  // float4 index, 4194304 total
    int c4 = idx & 63;
    float4 v  = ((const float4*)g_bufB)[idx];
    float4 sc = ((const float4*)g_coef)[c4];
    float4 sh = ((const float4*)(g_coef + 256))[c4];
    v.x = fmaxf(fmaf(v.x, sc.x, sh.x), 0.f);
    v.y = fmaxf(fmaf(v.y, sc.y, sh.y), 0.f);
    v.z = fmaxf(fmaf(v.z, sc.z, sh.z), 0.f);
    v.w = fmaxf(fmaf(v.w, sc.w, sh.w), 0.f);
    ((float4*)g_nodes)[idx] = v;
    ((float4*)g_bufA)[idx] = make_float4(0.f, 0.f, 0.f, 0.f);
}

// ---------------- edge scatter-add: agg[dst] += nodes[src] ----------------
__global__ void k_scatter(const void* __restrict__ ei, int E) {
    int e = blockIdx.x * 8 + (threadIdx.x >> 5);
    if (e >= E) return;
    int lane = threadIdx.x & 31;
    int src, dst;
    if (g_is32) {
        const int* p = (const int*)ei;
        src = p[e]; dst = p[E + e];
    } else {
        const long long* p = (const long long*)ei;
        src = (int)p[e]; dst = (int)p[E + e];
    }
    const float4* sp = (const float4*)&g_nodes[src * NC];
    float4* dp = (float4*)&g_bufA[dst * NC];
    #pragma unroll
    for (int i = 0; i < 2; i++) {
        float4 v = sp[lane + i * 32];
        float4* p4 = dp + lane + i * 32;
        asm volatile("red.global.add.v4.f32 [%0], {%1,%2,%3,%4};"
                     :: "l"(p4), "f"(v.x), "f"(v.y), "f"(v.z), "f"(v.w)
                     : "memory");
    }
}

// ---------------- graph GEMM: g = [agg|nodes] @ wcat + b_rel (f32x2) --------
__global__ __launch_bounds__(256) void k_gemm(const float* __restrict__ brel) {
    __shared__ float As[128 * 36];
    __shared__ float Bs[32 * 128];
    int mbase = blockIdx.x * 128;
    int nbase = blockIdx.y * 128;
    int tid = threadIdx.x;
    int tx = tid & 15, ty = tid >> 4;
    int m0 = ty * 8, n0 = tx * 8;
    u64 acc[8][4] = {};

    for (int kc = 0; kc < 16; kc++) {
        const float* src = (kc < 8) ? g_bufA : g_nodes;
        int coff = (kc & 7) * 32;
        #pragma unroll
        for (int i = 0; i < 4; i++) {
            int s = tid + i * 256;
            int m = s >> 3, cq = s & 7;
            *(float4*)&As[m * 36 + cq * 4] =
                *(const float4*)&src[(mbase + m) * NC + coff + cq * 4];
        }
        #pragma unroll
        for (int i = 0; i < 4; i++) {
            int s = tid + i * 256;
            int k = s >> 5, n4 = s & 31;
            *(float4*)&Bs[k * 128 + n4 * 4] =
                *(const float4*)&g_wcat[(kc * 32 + k) * NC + nbase + n4 * 4];
        }
        __syncthreads();
        #pragma unroll 8
        for (int kk = 0; kk < 32; kk++) {
            u64 aa[8];
            #pragma unroll
            for (int i = 0; i < 8; i++) aa[i] = pack_dup(As[(m0 + i) * 36 + kk]);
            const u64* bp = (const u64*)&Bs[kk * 128 + n0];
            u64 b0 = bp[0], b1 = bp[1], b2 = bp[2], b3 = bp[3];
            #pragma unroll
            for (int i = 0; i < 8; i++) {
                fma2(acc[i][0], aa[i], b0);
                fma2(acc[i][1], aa[i], b1);
                fma2(acc[i][2], aa[i], b2);
                fma2(acc[i][3], aa[i], b3);
            }
        }
        __syncthreads();
    }
    float bb[8];
    #pragma unroll
    for (int j = 0; j < 8; j++) bb[j] = brel[nbase + n0 + j];
    #pragma unroll
    for (int i = 0; i < 8; i++) {
        int row = mbase + m0 + i;
        float r[8];
        #pragma unroll
        for (int j = 0; j < 4; j++) unpack2(acc[i][j], r[2 * j], r[2 * j + 1]);
        float4 v0 = make_float4(r[0] + bb[0], r[1] + bb[1], r[2] + bb[2], r[3] + bb[3]);
        float4 v1 = make_float4(r[4] + bb[4], r[5] + bb[5], r[6] + bb[6], r[7] + bb[7]);
        *(float4*)&g_bufB[row * NC + nbase + n0] = v0;
        *(float4*)&g_bufB[row * NC + nbase + n0 + 4] = v1;
    }
}

// ---------------- bn1d+relu, transpose back to NCHW, residual ----------------
__global__ void k_final(const float* __restrict__ x, float* __restrict__ out) {
    __shared__ float tile[32 * 257];
    int bh = blockIdx.x;
    int b = bh >> 5, h = bh & 31;
    int nb = bh * 32;
    for (int i = threadIdx.x; i < 8192; i += 256) {
        int w = i >> 8, c = i & 255;
        tile[w * 257 + c] = g_bufB[(nb + w) * NC + c];
    }
    __syncthreads();
    for (int i = threadIdx.x; i < 8192; i += 256) {
        int c = i >> 5, w = i & 31;
        float v = fmaf(tile[w * 257 + c], g_coef[512 + c], g_coef[768 + c]);
        v = fmaxf(v, 0.f);
        int o = ((b * NC + c) * 32 + h) * 32 + w;
        out[o] = v + x[o];
    }
}

extern "C" void kernel_launch(void* const* d_in, const int* in_sizes, int n_in,
                              void* d_out, int out_size) {
    const float* x      = (const float*)d_in[0];
    const void*  ei     = d_in[1];
    const float* conv_w = (const float*)d_in[2];
    const float* conv_b = (const float*)d_in[3];
    const float* bn2d_g = (const float*)d_in[4];
    const float* bn2d_b = (const float*)d_in[5];
    const float* w_rel  = (const float*)d_in[6];
    const float* b_rel  = (const float*)d_in[7];
    const float* w_root = (const float*)d_in[8];
    const float* bn1d_g = (const float*)d_in[9];
    const float* bn1d_b = (const float*)d_in[10];
    float* out = (float*)d_out;
    int E = in_sizes[1] / 2;

    k_transpose_x<<<2048, 256>>>(x);
    k_prep<<<2304, 256>>>(conv_w, w_rel, w_root);
    k_detect<<<1, 256>>>((const int*)ei);
    k_conv<<<dim3(512, 2), 256>>>(conv_b);
    k_stats<<<1024, 256>>>(0);
    k_coef<<<1, 256>>>(0, bn2d_g, bn2d_b, 0);
    k_bnrelu_zero<<<16384, 256>>>();
    k_scatter<<<(E + 7) / 8, 256>>>(ei, E);
    k_gemm<<<dim3(512, 2), 256>>>(b_rel);
    k_stats<<<1024, 256>>>(512);
    k_coef<<<1, 256>>>(512, bn1d_g, bn1d_b, 512);
    k_final<<<2048, 256>>>(x, out);
}